// round 13
// baseline (speedup 1.0000x reference)
#include <cuda_runtime.h>
#include <cuda_fp16.h>
#include <cstdint>
#include <cstddef>

// ============================================================
// Problem constants
// ============================================================
#define MAX_E   320000
#define NRBF    16
#define DH      64
#define NW      288
#define CMUL    32

// ============================================================
// Compile-time Clebsch-Gordan (exact port of the reference math)
// ============================================================
struct CD { double re, im; };
__host__ __device__ constexpr CD cmulc(CD a, CD b){ return CD{a.re*b.re - a.im*b.im, a.re*b.im + a.im*b.re}; }
__host__ __device__ constexpr CD conjc(CD a){ return CD{a.re, -a.im}; }
__host__ __device__ constexpr double cfact(int n){ double r=1.0; for(int i=2;i<=n;++i) r*= (double)i; return r; }
__host__ __device__ constexpr double csqrt(double x){
  if (x <= 0.0) return 0.0;
  double r = x < 1.0 ? 1.0 : x;
  for (int i=0;i<200;++i) r = 0.5*(r + x/r);
  return r;
}
__host__ __device__ constexpr double cgc(int l1,int l2,int l3,int m1,int m2){
  int m3 = m1+m2;
  if (m3 < -l3 || m3 > l3) return 0.0;
  double pref = csqrt((double)(2*l3+1)*cfact(l1+l2-l3)*cfact(l1-l2+l3)*cfact(-l1+l2+l3)/cfact(l1+l2+l3+1));
  pref *= csqrt(cfact(l3+m3)*cfact(l3-m3)*cfact(l1-m1)*cfact(l1+m1)*cfact(l2-m2)*cfact(l2+m2));
  double s = 0.0;
  for (int k=0;k<=l1+l2-l3;++k){
    int a1=l1+l2-l3-k, a2=l1-m1-k, a3=l2+m2-k, a4=l3-l2+m1+k, a5=l3-l1-m2+k;
    if (a1<0||a2<0||a3<0||a4<0||a5<0) continue;
    double d = cfact(k)*cfact(a1)*cfact(a2)*cfact(a3)*cfact(a4)*cfact(a5);
    s += ((k&1)? -1.0 : 1.0)/d;
  }
  return pref*s;
}
struct UMat { CD u[5][5]; };
__host__ __device__ constexpr UMat makeU(int l){
  UMat U{};
  const double s = 1.0/csqrt(2.0);
  U.u[l][l] = CD{1.0, 0.0};
  for (int m=1;m<=l;++m){
    double sg = (m&1)? -1.0 : 1.0;
    U.u[l+m][l+m] = CD{sg*s, 0.0};
    U.u[l+m][l-m] = CD{s, 0.0};
    U.u[l-m][l-m] = CD{0.0, s};
    U.u[l-m][l+m] = CD{0.0, -sg*s};
  }
  return U;
}
struct CG3 { double v[5][5][5]; };
__host__ __device__ constexpr CG3 make_cg(int l1,int l2,int l3){
  UMat U1 = makeU(l1), U2 = makeU(l2), U3 = makeU(l3);
  int n1=2*l1+1, n2=2*l2+1, n3=2*l3+1;
  double tre[5][5][5] = {}, tim[5][5][5] = {};
  double mre=0.0, mim=0.0;
  for (int a=0;a<n1;++a) for (int b=0;b<n2;++b) for (int c=0;c<n3;++c){
    CD acc{0.0,0.0};
    for (int m=0;m<n1;++m) for (int n=0;n<n2;++n){
      int o = (m-l1)+(n-l2)+l3;
      if (o < 0 || o >= n3) continue;
      double cg = cgc(l1,l2,l3, m-l1, n-l2);
      if (cg == 0.0) continue;
      CD t = cmulc(cmulc(U1.u[a][m], U2.u[b][n]), conjc(U3.u[c][o]));
      acc.re += t.re*cg; acc.im += t.im*cg;
    }
    tre[a][b][c]=acc.re; tim[a][b][c]=acc.im;
    double ar = acc.re<0.0?-acc.re:acc.re;
    double ai = acc.im<0.0?-acc.im:acc.im;
    if (ar>mre) mre=ar;
    if (ai>mim) mim=ai;
  }
  CG3 R{};
  for (int a=0;a<n1;++a) for (int b=0;b<n2;++b) for (int c=0;c<n3;++c){
    double vv = (mre >= mim) ? tre[a][b][c] : tim[a][b][c];
    if (vv < 1e-12 && vv > -1e-12) vv = 0.0;
    R.v[a][b][c] = vv;
  }
  return R;
}

// tanh-based silu: silu(x) = h + h*tanh(h), h = x/2.
__device__ __forceinline__ float silu_t(float x){
  float h = 0.5f * x;
  float t;
  asm("tanh.approx.f32 %0, %1;" : "=f"(t) : "f"(h));
  return fmaf(h, t, h);
}

#define INV2048 4.8828125e-4f

// ============================================================
// mma.sync m16n8k16 fp16 + ldmatrix
// ============================================================
__device__ __forceinline__ void mma16816(float d[4], const uint32_t a[4], const uint32_t b[2]){
  asm volatile("mma.sync.aligned.m16n8k16.row.col.f32.f16.f16.f32 "
    "{%0,%1,%2,%3}, {%4,%5,%6,%7}, {%8,%9}, {%0,%1,%2,%3};"
    : "+f"(d[0]), "+f"(d[1]), "+f"(d[2]), "+f"(d[3])
    : "r"(a[0]), "r"(a[1]), "r"(a[2]), "r"(a[3]), "r"(b[0]), "r"(b[1]));
}
__device__ __forceinline__ void ldm4(uint32_t addr, uint32_t* r){
  asm volatile("ldmatrix.sync.aligned.m8n8.x4.shared.b16 {%0,%1,%2,%3}, [%4];"
    : "=r"(r[0]), "=r"(r[1]), "=r"(r[2]), "=r"(r[3]) : "r"(addr));
}

// split into fp16 hi + fp16 residual scaled by 2048
__device__ __forceinline__ void split2h(float y0, float y1, uint32_t& hi, uint32_t& lo){
  uint32_t h;
  asm("cvt.rn.f16x2.f32 %0, %1, %2;" : "=r"(h) : "f"(y1), "f"(y0));
  __half2 hh = *reinterpret_cast<__half2*>(&h);
  float2 hf = __half22float2(hh);
  float r0 = (y0 - hf.x) * 2048.0f;
  float r1 = (y1 - hf.y) * 2048.0f;
  uint32_t l;
  asm("cvt.rn.f16x2.f32 %0, %1, %2;" : "=r"(l) : "f"(r1), "f"(r0));
  hi = h; lo = l;
}
__device__ __forceinline__ uint32_t pack_h2(float y0, float y1){
  uint32_t h;
  asm("cvt.rn.f16x2.f32 %0, %1, %2;" : "=r"(h) : "f"(y1), "f"(y0));
  return h;
}

// ============================================================
// SMEM layout (bytes).
// ============================================================
#define SM_W0   0          // 64 * 48   = 3072
#define SM_W1   3072       // 64 * 144  = 9216
#define SM_W2   12288      // 288 * 144 = 41472
#define WB_ROW  592
#define WB_WARP (16*WB_ROW)            // 9472
#define SM_WBUF 53760
#define SM_SB   (SM_WBUF + 16*WB_WARP) // 205312
#define SM_TOT  (SM_SB + 16*NW*4)      // 223744

#define FT_THREADS 512   // 16 warps, each autonomous on 16-edge tiles

template<int L1, int L2, int L3>
__device__ __forceinline__ void do_path(float wp, const float* x, const float* Y, float* o){
  constexpr CG3 cg = make_cg(L1, L2, L3);
  #pragma unroll
  for (int a = 0; a < 2*L1+1; ++a){
    float wx = wp * x[a];
    #pragma unroll
    for (int b = 0; b < 2*L2+1; ++b){
      #pragma unroll
      for (int c = 0; c < 2*L3+1; ++c){
        const float v = (float)cg.v[a][b][c];
        if (v != 0.0f) o[c] += wx * (v * Y[b]);
      }
    }
  }
}

// Compute the 9-float message for one (edge, channel=lane) unit.
// o[0] = l0 part; o[1..3] = l1; o[4..8] = l2.
__device__ __forceinline__ void compute_o(int e, int lane,
                                          const float* __restrict__ nf,
                                          const float* __restrict__ evec,
                                          const int*   __restrict__ eidx,
                                          const char*  wb_row,
                                          float* o, int& dst){
  int src = eidx[2*e+0];
  dst = eidx[2*e+1];

  float vx = evec[3*(size_t)e+0];
  float vy = evec[3*(size_t)e+1];
  float vz = evec[3*(size_t)e+2];
  float nrm = sqrtf(vx*vx + vy*vy + vz*vz);
  float inv = __fdividef(1.0f, nrm + 1e-12f);
  float X = vx*inv, Yv = vy*inv, Z = vz*inv;
  const float S3 = 1.7320508075688772f;
  float Y0a[1] = {1.0f};
  float Y1a[3] = {Yv, Z, X};
  float Y2a[5] = {S3*X*Yv, S3*Yv*Z, 0.5f*(3.0f*Z*Z - 1.0f), S3*X*Z, 0.5f*S3*(X*X - Yv*Yv)};

  const float* nfr = nf + (size_t)src * (4*CMUL);
  float x0[1] = { nfr[lane] };
  float x1[3] = { nfr[CMUL + 3*lane + 0],
                  nfr[CMUL + 3*lane + 1],
                  nfr[CMUL + 3*lane + 2] };

  const __half* wr = (const __half*)wb_row;
  float wp0 = __half2float(wr[0*CMUL + lane]);
  float wp1 = __half2float(wr[1*CMUL + lane]);
  float wp2 = __half2float(wr[2*CMUL + lane]);
  float wp3 = __half2float(wr[3*CMUL + lane]);
  float wp4 = __half2float(wr[4*CMUL + lane]);
  float wp5 = __half2float(wr[5*CMUL + lane]);
  float wp6 = __half2float(wr[6*CMUL + lane]);
  float wp7 = __half2float(wr[7*CMUL + lane]);
  float wp8 = __half2float(wr[8*CMUL + lane]);

  float* o0 = o;      // 1
  float* o1 = o + 1;  // 3
  float* o2 = o + 4;  // 5
  #pragma unroll
  for (int q = 0; q < 9; ++q) o[q] = 0.f;

  do_path<0,0,0>(wp0, x0, Y0a, o0);
  do_path<0,1,1>(wp1, x0, Y1a, o1);
  do_path<0,2,2>(wp2, x0, Y2a, o2);
  do_path<1,0,1>(wp3, x1, Y0a, o1);
  do_path<1,1,0>(wp4, x1, Y1a, o0);
  do_path<1,1,1>(wp5, x1, Y1a, o1);
  do_path<1,1,2>(wp6, x1, Y1a, o2);
  do_path<1,2,1>(wp7, x1, Y2a, o1);
  do_path<1,2,2>(wp8, x1, Y2a, o2);
}

// Stage + coalesced atomic tail for one edge.
__device__ __forceinline__ void tp_tail(const float* o, int dst, int lane,
                                        float* sbw, float* __restrict__ out){
  sbw[lane] = o[0];
  #pragma unroll
  for (int c = 0; c < 3; ++c) sbw[CMUL + 3*lane + c] = o[1+c];
  #pragma unroll
  for (int c = 0; c < 5; ++c) sbw[4*CMUL + 5*lane + c] = o[4+c];
  __syncwarp();
  float* orow = out + (size_t)dst * NW;
  #pragma unroll
  for (int p = 0; p < 9; ++p)
    atomicAdd(orow + p*32 + lane, sbw[p*32 + lane]);
  __syncwarp();
}

__global__ __launch_bounds__(FT_THREADS)
void fused_kernel(const float* __restrict__ nf,
                  const float* __restrict__ ef,
                  const float* __restrict__ evec,
                  const int*   __restrict__ eidx,
                  const float* __restrict__ W0,
                  const float* __restrict__ W1,
                  const float* __restrict__ W2,
                  float* __restrict__ out,
                  int E){
  extern __shared__ char sm[];
  uint32_t sm32 = (uint32_t)__cvta_generic_to_shared(sm);
  int t = threadIdx.x;
  int lane = t & 31, wid = t >> 5;
  int grp = lane >> 2, qt = lane & 3;

  const uint32_t offB48  = (uint32_t)(lane>>4)*384  + (uint32_t)(lane&7)*48  + (uint32_t)((lane>>3)&1)*16;
  const uint32_t offB144 = (uint32_t)(lane>>4)*1152 + (uint32_t)(lane&7)*144 + (uint32_t)((lane>>3)&1)*16;

  // ---- stage fp16 weights once ----
  for (int idx = t; idx < 16*64; idx += FT_THREADS){
    int k = idx >> 6, n = idx & 63;
    *(__half*)(sm + SM_W0 + n*48 + k*2) = __float2half_rn(W0[idx]);
  }
  for (int idx = t; idx < 64*64; idx += FT_THREADS){
    int k = idx >> 6, n = idx & 63;
    *(__half*)(sm + SM_W1 + n*144 + k*2) = __float2half_rn(W1[idx]);
  }
  for (int idx = t; idx < 64*288; idx += FT_THREADS){
    int k = idx / 288, n = idx % 288;
    *(__half*)(sm + SM_W2 + n*144 + k*2) = __float2half_rn(W2[idx]);
  }
  __syncthreads();   // only block barrier in the kernel

  char* wb = sm + SM_WBUF + wid * WB_WARP;
  float* sbw = (float*)(sm + SM_SB + wid * NW * 4);

  int ntiles = (E + 15) >> 4;
  int gwarp  = blockIdx.x * (FT_THREADS/32) + wid;
  int stride = gridDim.x * (FT_THREADS/32);

  for (int tl = gwarp; tl < ntiles; tl += stride){
    int base_e = tl * 16;
    int e0 = base_e + grp;
    int e1 = e0 + 8;
    int ec0 = (e0 < E) ? e0 : E-1;
    int ec1 = (e1 < E) ? e1 : E-1;

    // ---- A1 fragments straight from ef (hi + scaled residual) ----
    uint32_t a1h[4], a1l[4];
    {
      float2 p00 = *(const float2*)(ef + (size_t)ec0*NRBF + 2*qt);
      float2 p10 = *(const float2*)(ef + (size_t)ec1*NRBF + 2*qt);
      float2 p01 = *(const float2*)(ef + (size_t)ec0*NRBF + 8 + 2*qt);
      float2 p11 = *(const float2*)(ef + (size_t)ec1*NRBF + 8 + 2*qt);
      split2h(p00.x, p00.y, a1h[0], a1l[0]);
      split2h(p10.x, p10.y, a1h[1], a1l[1]);
      split2h(p01.x, p01.y, a1h[2], a1l[2]);
      split2h(p11.x, p11.y, a1h[3], a1l[3]);
    }

    // ---- Layer 1: 16 -> 64, A split-2 ----
    uint32_t a2h[4][4], a2l[4][4];
    #pragma unroll
    for (int g = 0; g < 2; ++g){
      float accA[4][4], accB[4][4];
      #pragma unroll
      for (int j=0;j<4;++j)
        #pragma unroll
        for (int q=0;q<4;++q){ accA[j][q]=0.f; accB[j][q]=0.f; }
      uint32_t b01[4], b23[4];
      ldm4(sm32 + SM_W0 + (uint32_t)((g*4+0)*8)*48 + offB48, b01);
      ldm4(sm32 + SM_W0 + (uint32_t)((g*4+2)*8)*48 + offB48, b23);
      mma16816(accA[0], a1h, b01+0); mma16816(accA[1], a1h, b01+2);
      mma16816(accA[2], a1h, b23+0); mma16816(accA[3], a1h, b23+2);
      mma16816(accB[0], a1l, b01+0); mma16816(accB[1], a1l, b01+2);
      mma16816(accB[2], a1l, b23+0); mma16816(accB[3], a1l, b23+2);
      #pragma unroll
      for (int j=0;j<4;++j){
        int nt = g*4 + j, ks = nt >> 1, ix = (nt & 1) * 2;
        float y0 = silu_t(fmaf(accB[j][0], INV2048, accA[j][0]));
        float y1 = silu_t(fmaf(accB[j][1], INV2048, accA[j][1]));
        float y2 = silu_t(fmaf(accB[j][2], INV2048, accA[j][2]));
        float y3 = silu_t(fmaf(accB[j][3], INV2048, accA[j][3]));
        split2h(y0, y1, a2h[ks][ix],   a2l[ks][ix]);
        split2h(y2, y3, a2h[ks][ix+1], a2l[ks][ix+1]);
      }
    }

    // ---- Layer 2: 64 -> 64, A split-2; output hi-only fragments ----
    uint32_t a3h[4][4];
    #pragma unroll
    for (int g = 0; g < 2; ++g){
      float accA[4][4], accB[4][4];
      #pragma unroll
      for (int j=0;j<4;++j)
        #pragma unroll
        for (int q=0;q<4;++q){ accA[j][q]=0.f; accB[j][q]=0.f; }
      #pragma unroll
      for (int ks = 0; ks < 4; ++ks){
        uint32_t b01[4], b23[4];
        ldm4(sm32 + SM_W1 + (uint32_t)((g*4+0)*8)*144 + (uint32_t)ks*32 + offB144, b01);
        ldm4(sm32 + SM_W1 + (uint32_t)((g*4+2)*8)*144 + (uint32_t)ks*32 + offB144, b23);
        mma16816(accA[0], a2h[ks], b01+0); mma16816(accA[1], a2h[ks], b01+2);
        mma16816(accA[2], a2h[ks], b23+0); mma16816(accA[3], a2h[ks], b23+2);
        mma16816(accB[0], a2l[ks], b01+0); mma16816(accB[1], a2l[ks], b01+2);
        mma16816(accB[2], a2l[ks], b23+0); mma16816(accB[3], a2l[ks], b23+2);
      }
      #pragma unroll
      for (int j=0;j<4;++j){
        int nt = g*4 + j, ks = nt >> 1, ix = (nt & 1) * 2;
        float y0 = silu_t(fmaf(accB[j][0], INV2048, accA[j][0]));
        float y1 = silu_t(fmaf(accB[j][1], INV2048, accA[j][1]));
        float y2 = silu_t(fmaf(accB[j][2], INV2048, accA[j][2]));
        float y3 = silu_t(fmaf(accB[j][3], INV2048, accA[j][3]));
        a3h[ks][ix]   = pack_h2(y0, y1);
        a3h[ks][ix+1] = pack_h2(y2, y3);
      }
    }

    // ---- Layer 3: 64 -> 288, A hi-only; write into per-warp wbuf ----
    #pragma unroll 1
    for (int g = 0; g < 9; ++g){
      float accA[4][4];
      #pragma unroll
      for (int j=0;j<4;++j)
        #pragma unroll
        for (int q=0;q<4;++q) accA[j][q]=0.f;
      #pragma unroll
      for (int ks = 0; ks < 4; ++ks){
        uint32_t b01[4], b23[4];
        ldm4(sm32 + SM_W2 + (uint32_t)((g*4+0)*8)*144 + (uint32_t)ks*32 + offB144, b01);
        ldm4(sm32 + SM_W2 + (uint32_t)((g*4+2)*8)*144 + (uint32_t)ks*32 + offB144, b23);
        mma16816(accA[0], a3h[ks], b01+0); mma16816(accA[1], a3h[ks], b01+2);
        mma16816(accA[2], a3h[ks], b23+0); mma16816(accA[3], a3h[ks], b23+2);
      }
      #pragma unroll
      for (int j=0;j<4;++j){
        int col = (g*4+j)*8 + 2*qt;
        float y0 = silu_t(accA[j][0]);
        float y1 = silu_t(accA[j][1]);
        float y2 = silu_t(accA[j][2]);
        float y3 = silu_t(accA[j][3]);
        *(uint32_t*)(wb + grp*WB_ROW + col*2)     = pack_h2(y0, y1);
        *(uint32_t*)(wb + (grp+8)*WB_ROW + col*2) = pack_h2(y2, y3);
      }
    }
    __syncwarp();

    // ---- TP phase: 2-stage software pipeline over edges ----
    int ecount = E - base_e;
    if (ecount > 16) ecount = 16;

    float oA[9]; int dstA;
    compute_o(base_e, lane, nf, evec, eidx, wb, oA, dstA);

    #pragma unroll 1
    for (int el = 0; el < ecount; ++el){
      float oB[9]; int dstB = 0;
      if (el + 1 < ecount)
        compute_o(base_e + el + 1, lane, nf, evec, eidx, wb + (el+1)*WB_ROW, oB, dstB);

      tp_tail(oA, dstA, lane, sbw, out);

      if (el + 1 < ecount){
        #pragma unroll
        for (int q = 0; q < 9; ++q) oA[q] = oB[q];
        dstA = dstB;
      }
    }
  }
}

// ============================================================
// Launch
// ============================================================
extern "C" void kernel_launch(void* const* d_in, const int* in_sizes, int n_in,
                              void* d_out, int out_size){
  const float* nf = (const float*)d_in[0];
  const float* ef = (const float*)d_in[1];
  const float* ev = (const float*)d_in[2];
  const int*   ei = (const int*)  d_in[3];
  const float* W0 = (const float*)d_in[4];
  const float* W1 = (const float*)d_in[5];
  const float* W2 = (const float*)d_in[6];
  float* out = (float*)d_out;

  int E = in_sizes[2] / 3;
  if (E > MAX_E) E = MAX_E;

  cudaMemsetAsync(d_out, 0, (size_t)out_size * sizeof(float), 0);

  cudaFuncSetAttribute(fused_kernel, cudaFuncAttributeMaxDynamicSharedMemorySize, SM_TOT);
  fused_kernel<<<148, FT_THREADS, SM_TOT>>>(nf, ef, ev, ei, W0, W1, W2, out, E);
}

// round 14
// speedup vs baseline: 1.1470x; 1.1470x over previous
#include <cuda_runtime.h>
#include <cuda_fp16.h>
#include <cstdint>
#include <cstddef>

// ============================================================
// Problem constants
// ============================================================
#define MAX_E   320000
#define NRBF    16
#define DH      64
#define NW      288
#define CMUL    32

// ============================================================
// Compile-time Clebsch-Gordan (exact port of the reference math)
// ============================================================
struct CD { double re, im; };
__host__ __device__ constexpr CD cmulc(CD a, CD b){ return CD{a.re*b.re - a.im*b.im, a.re*b.im + a.im*b.re}; }
__host__ __device__ constexpr CD conjc(CD a){ return CD{a.re, -a.im}; }
__host__ __device__ constexpr double cfact(int n){ double r=1.0; for(int i=2;i<=n;++i) r*= (double)i; return r; }
__host__ __device__ constexpr double csqrt(double x){
  if (x <= 0.0) return 0.0;
  double r = x < 1.0 ? 1.0 : x;
  for (int i=0;i<200;++i) r = 0.5*(r + x/r);
  return r;
}
__host__ __device__ constexpr double cgc(int l1,int l2,int l3,int m1,int m2){
  int m3 = m1+m2;
  if (m3 < -l3 || m3 > l3) return 0.0;
  double pref = csqrt((double)(2*l3+1)*cfact(l1+l2-l3)*cfact(l1-l2+l3)*cfact(-l1+l2+l3)/cfact(l1+l2+l3+1));
  pref *= csqrt(cfact(l3+m3)*cfact(l3-m3)*cfact(l1-m1)*cfact(l1+m1)*cfact(l2-m2)*cfact(l2+m2));
  double s = 0.0;
  for (int k=0;k<=l1+l2-l3;++k){
    int a1=l1+l2-l3-k, a2=l1-m1-k, a3=l2+m2-k, a4=l3-l2+m1+k, a5=l3-l1-m2+k;
    if (a1<0||a2<0||a3<0||a4<0||a5<0) continue;
    double d = cfact(k)*cfact(a1)*cfact(a2)*cfact(a3)*cfact(a4)*cfact(a5);
    s += ((k&1)? -1.0 : 1.0)/d;
  }
  return pref*s;
}
struct UMat { CD u[5][5]; };
__host__ __device__ constexpr UMat makeU(int l){
  UMat U{};
  const double s = 1.0/csqrt(2.0);
  U.u[l][l] = CD{1.0, 0.0};
  for (int m=1;m<=l;++m){
    double sg = (m&1)? -1.0 : 1.0;
    U.u[l+m][l+m] = CD{sg*s, 0.0};
    U.u[l+m][l-m] = CD{s, 0.0};
    U.u[l-m][l-m] = CD{0.0, s};
    U.u[l-m][l+m] = CD{0.0, -sg*s};
  }
  return U;
}
struct CG3 { double v[5][5][5]; };
__host__ __device__ constexpr CG3 make_cg(int l1,int l2,int l3){
  UMat U1 = makeU(l1), U2 = makeU(l2), U3 = makeU(l3);
  int n1=2*l1+1, n2=2*l2+1, n3=2*l3+1;
  double tre[5][5][5] = {}, tim[5][5][5] = {};
  double mre=0.0, mim=0.0;
  for (int a=0;a<n1;++a) for (int b=0;b<n2;++b) for (int c=0;c<n3;++c){
    CD acc{0.0,0.0};
    for (int m=0;m<n1;++m) for (int n=0;n<n2;++n){
      int o = (m-l1)+(n-l2)+l3;
      if (o < 0 || o >= n3) continue;
      double cg = cgc(l1,l2,l3, m-l1, n-l2);
      if (cg == 0.0) continue;
      CD t = cmulc(cmulc(U1.u[a][m], U2.u[b][n]), conjc(U3.u[c][o]));
      acc.re += t.re*cg; acc.im += t.im*cg;
    }
    tre[a][b][c]=acc.re; tim[a][b][c]=acc.im;
    double ar = acc.re<0.0?-acc.re:acc.re;
    double ai = acc.im<0.0?-acc.im:acc.im;
    if (ar>mre) mre=ar;
    if (ai>mim) mim=ai;
  }
  CG3 R{};
  for (int a=0;a<n1;++a) for (int b=0;b<n2;++b) for (int c=0;c<n3;++c){
    double vv = (mre >= mim) ? tre[a][b][c] : tim[a][b][c];
    if (vv < 1e-12 && vv > -1e-12) vv = 0.0;
    R.v[a][b][c] = vv;
  }
  return R;
}

// tanh-based silu: silu(x) = h + h*tanh(h), h = x/2.
__device__ __forceinline__ float silu_t(float x){
  float h = 0.5f * x;
  float t;
  asm("tanh.approx.f32 %0, %1;" : "=f"(t) : "f"(h));
  return fmaf(h, t, h);
}

#define INV2048 4.8828125e-4f

// ============================================================
// mma.sync m16n8k16 fp16 + ldmatrix
// ============================================================
__device__ __forceinline__ void mma16816(float d[4], const uint32_t a[4], const uint32_t b[2]){
  asm volatile("mma.sync.aligned.m16n8k16.row.col.f32.f16.f16.f32 "
    "{%0,%1,%2,%3}, {%4,%5,%6,%7}, {%8,%9}, {%0,%1,%2,%3};"
    : "+f"(d[0]), "+f"(d[1]), "+f"(d[2]), "+f"(d[3])
    : "r"(a[0]), "r"(a[1]), "r"(a[2]), "r"(a[3]), "r"(b[0]), "r"(b[1]));
}
__device__ __forceinline__ void ldm4(uint32_t addr, uint32_t* r){
  asm volatile("ldmatrix.sync.aligned.m8n8.x4.shared.b16 {%0,%1,%2,%3}, [%4];"
    : "=r"(r[0]), "=r"(r[1]), "=r"(r[2]), "=r"(r[3]) : "r"(addr));
}

// split into fp16 hi + fp16 residual scaled by 2048
__device__ __forceinline__ void split2h(float y0, float y1, uint32_t& hi, uint32_t& lo){
  uint32_t h;
  asm("cvt.rn.f16x2.f32 %0, %1, %2;" : "=r"(h) : "f"(y1), "f"(y0));
  __half2 hh = *reinterpret_cast<__half2*>(&h);
  float2 hf = __half22float2(hh);
  float r0 = (y0 - hf.x) * 2048.0f;
  float r1 = (y1 - hf.y) * 2048.0f;
  uint32_t l;
  asm("cvt.rn.f16x2.f32 %0, %1, %2;" : "=r"(l) : "f"(r1), "f"(r0));
  hi = h; lo = l;
}
__device__ __forceinline__ uint32_t pack_h2(float y0, float y1){
  uint32_t h;
  asm("cvt.rn.f16x2.f32 %0, %1, %2;" : "=r"(h) : "f"(y1), "f"(y0));
  return h;
}

// ============================================================
// SMEM layout (bytes).
// ============================================================
#define SM_W0   0          // 64 * 48   = 3072
#define SM_W1   3072       // 64 * 144  = 9216
#define SM_W2   12288      // 288 * 144 = 41472
#define WB_ROW  592
#define WB_WARP (16*WB_ROW)            // 9472
#define SM_WBUF 53760
#define SM_SB   (SM_WBUF + 16*WB_WARP) // 205312
#define SM_TOT  (SM_SB + 16*NW*4)      // 223744

#define FT_THREADS 512   // 16 warps, each autonomous on 16-edge tiles

template<int L1, int L2, int L3>
__device__ __forceinline__ void do_path(float wp, const float* x, const float* Y, float* o){
  constexpr CG3 cg = make_cg(L1, L2, L3);
  #pragma unroll
  for (int a = 0; a < 2*L1+1; ++a){
    float wx = wp * x[a];
    #pragma unroll
    for (int b = 0; b < 2*L2+1; ++b){
      #pragma unroll
      for (int c = 0; c < 2*L3+1; ++c){
        const float v = (float)cg.v[a][b][c];
        if (v != 0.0f) o[c] += wx * (v * Y[b]);
      }
    }
  }
}

struct Pref {
  int dst;
  float vx, vy, vz;
  float x0, x1a, x1b, x1c;
};

__device__ __forceinline__ void pf_load(Pref& p, int e, int lane,
                                        const float* __restrict__ nf,
                                        const float* __restrict__ evec,
                                        const int*   __restrict__ eidx){
  int src = eidx[2*e+0];
  p.dst   = eidx[2*e+1];
  p.vx = evec[3*(size_t)e+0];
  p.vy = evec[3*(size_t)e+1];
  p.vz = evec[3*(size_t)e+2];
  const float* nfr = nf + (size_t)src * (4*CMUL);
  p.x0  = nfr[lane];
  p.x1a = nfr[CMUL + 3*lane + 0];
  p.x1b = nfr[CMUL + 3*lane + 1];
  p.x1c = nfr[CMUL + 3*lane + 2];
}

__global__ __launch_bounds__(FT_THREADS)
void fused_kernel(const float* __restrict__ nf,
                  const float* __restrict__ ef,
                  const float* __restrict__ evec,
                  const int*   __restrict__ eidx,
                  const float* __restrict__ W0,
                  const float* __restrict__ W1,
                  const float* __restrict__ W2,
                  float* __restrict__ out,
                  int E){
  extern __shared__ char sm[];
  uint32_t sm32 = (uint32_t)__cvta_generic_to_shared(sm);
  int t = threadIdx.x;
  int lane = t & 31, wid = t >> 5;
  int grp = lane >> 2, qt = lane & 3;

  const uint32_t offB48  = (uint32_t)(lane>>4)*384  + (uint32_t)(lane&7)*48  + (uint32_t)((lane>>3)&1)*16;
  const uint32_t offB144 = (uint32_t)(lane>>4)*1152 + (uint32_t)(lane&7)*144 + (uint32_t)((lane>>3)&1)*16;

  // ---- stage fp16 weights once ----
  for (int idx = t; idx < 16*64; idx += FT_THREADS){
    int k = idx >> 6, n = idx & 63;
    *(__half*)(sm + SM_W0 + n*48 + k*2) = __float2half_rn(W0[idx]);
  }
  for (int idx = t; idx < 64*64; idx += FT_THREADS){
    int k = idx >> 6, n = idx & 63;
    *(__half*)(sm + SM_W1 + n*144 + k*2) = __float2half_rn(W1[idx]);
  }
  for (int idx = t; idx < 64*288; idx += FT_THREADS){
    int k = idx / 288, n = idx % 288;
    *(__half*)(sm + SM_W2 + n*144 + k*2) = __float2half_rn(W2[idx]);
  }
  __syncthreads();   // only block barrier in the kernel

  char* wb = sm + SM_WBUF + wid * WB_WARP;
  float* sbw = (float*)(sm + SM_SB + wid * NW * 4);

  int ntiles = (E + 15) >> 4;
  int gwarp  = blockIdx.x * (FT_THREADS/32) + wid;
  int stride = gridDim.x * (FT_THREADS/32);

  for (int tl = gwarp; tl < ntiles; tl += stride){
    int base_e = tl * 16;
    int e0 = base_e + grp;
    int e1 = e0 + 8;
    int ec0 = (e0 < E) ? e0 : E-1;
    int ec1 = (e1 < E) ? e1 : E-1;

    // ---- A1 fragments straight from ef (hi + scaled residual) ----
    uint32_t a1h[4], a1l[4];
    {
      float2 p00 = *(const float2*)(ef + (size_t)ec0*NRBF + 2*qt);
      float2 p10 = *(const float2*)(ef + (size_t)ec1*NRBF + 2*qt);
      float2 p01 = *(const float2*)(ef + (size_t)ec0*NRBF + 8 + 2*qt);
      float2 p11 = *(const float2*)(ef + (size_t)ec1*NRBF + 8 + 2*qt);
      split2h(p00.x, p00.y, a1h[0], a1l[0]);
      split2h(p10.x, p10.y, a1h[1], a1l[1]);
      split2h(p01.x, p01.y, a1h[2], a1l[2]);
      split2h(p11.x, p11.y, a1h[3], a1l[3]);
    }

    // ---- Layer 1: 16 -> 64, A split-2 ----
    uint32_t a2h[4][4], a2l[4][4];
    #pragma unroll
    for (int g = 0; g < 2; ++g){
      float accA[4][4], accB[4][4];
      #pragma unroll
      for (int j=0;j<4;++j)
        #pragma unroll
        for (int q=0;q<4;++q){ accA[j][q]=0.f; accB[j][q]=0.f; }
      uint32_t b01[4], b23[4];
      ldm4(sm32 + SM_W0 + (uint32_t)((g*4+0)*8)*48 + offB48, b01);
      ldm4(sm32 + SM_W0 + (uint32_t)((g*4+2)*8)*48 + offB48, b23);
      mma16816(accA[0], a1h, b01+0); mma16816(accA[1], a1h, b01+2);
      mma16816(accA[2], a1h, b23+0); mma16816(accA[3], a1h, b23+2);
      mma16816(accB[0], a1l, b01+0); mma16816(accB[1], a1l, b01+2);
      mma16816(accB[2], a1l, b23+0); mma16816(accB[3], a1l, b23+2);
      #pragma unroll
      for (int j=0;j<4;++j){
        int nt = g*4 + j, ks = nt >> 1, ix = (nt & 1) * 2;
        float y0 = silu_t(fmaf(accB[j][0], INV2048, accA[j][0]));
        float y1 = silu_t(fmaf(accB[j][1], INV2048, accA[j][1]));
        float y2 = silu_t(fmaf(accB[j][2], INV2048, accA[j][2]));
        float y3 = silu_t(fmaf(accB[j][3], INV2048, accA[j][3]));
        split2h(y0, y1, a2h[ks][ix],   a2l[ks][ix]);
        split2h(y2, y3, a2h[ks][ix+1], a2l[ks][ix+1]);
      }
    }

    // ---- Layer 2: 64 -> 64, A split-2; output hi-only fragments ----
    uint32_t a3h[4][4];
    #pragma unroll
    for (int g = 0; g < 2; ++g){
      float accA[4][4], accB[4][4];
      #pragma unroll
      for (int j=0;j<4;++j)
        #pragma unroll
        for (int q=0;q<4;++q){ accA[j][q]=0.f; accB[j][q]=0.f; }
      #pragma unroll
      for (int ks = 0; ks < 4; ++ks){
        uint32_t b01[4], b23[4];
        ldm4(sm32 + SM_W1 + (uint32_t)((g*4+0)*8)*144 + (uint32_t)ks*32 + offB144, b01);
        ldm4(sm32 + SM_W1 + (uint32_t)((g*4+2)*8)*144 + (uint32_t)ks*32 + offB144, b23);
        mma16816(accA[0], a2h[ks], b01+0); mma16816(accA[1], a2h[ks], b01+2);
        mma16816(accA[2], a2h[ks], b23+0); mma16816(accA[3], a2h[ks], b23+2);
        mma16816(accB[0], a2l[ks], b01+0); mma16816(accB[1], a2l[ks], b01+2);
        mma16816(accB[2], a2l[ks], b23+0); mma16816(accB[3], a2l[ks], b23+2);
      }
      #pragma unroll
      for (int j=0;j<4;++j){
        int nt = g*4 + j, ks = nt >> 1, ix = (nt & 1) * 2;
        float y0 = silu_t(fmaf(accB[j][0], INV2048, accA[j][0]));
        float y1 = silu_t(fmaf(accB[j][1], INV2048, accA[j][1]));
        float y2 = silu_t(fmaf(accB[j][2], INV2048, accA[j][2]));
        float y3 = silu_t(fmaf(accB[j][3], INV2048, accA[j][3]));
        a3h[ks][ix]   = pack_h2(y0, y1);
        a3h[ks][ix+1] = pack_h2(y2, y3);
      }
    }

    // ---- Layer 3: 64 -> 288, A hi-only; write into per-warp wbuf ----
    #pragma unroll 1
    for (int g = 0; g < 9; ++g){
      float accA[4][4];
      #pragma unroll
      for (int j=0;j<4;++j)
        #pragma unroll
        for (int q=0;q<4;++q) accA[j][q]=0.f;
      #pragma unroll
      for (int ks = 0; ks < 4; ++ks){
        uint32_t b01[4], b23[4];
        ldm4(sm32 + SM_W2 + (uint32_t)((g*4+0)*8)*144 + (uint32_t)ks*32 + offB144, b01);
        ldm4(sm32 + SM_W2 + (uint32_t)((g*4+2)*8)*144 + (uint32_t)ks*32 + offB144, b23);
        mma16816(accA[0], a3h[ks], b01+0); mma16816(accA[1], a3h[ks], b01+2);
        mma16816(accA[2], a3h[ks], b23+0); mma16816(accA[3], a3h[ks], b23+2);
      }
      #pragma unroll
      for (int j=0;j<4;++j){
        int col = (g*4+j)*8 + 2*qt;
        float y0 = silu_t(accA[j][0]);
        float y1 = silu_t(accA[j][1]);
        float y2 = silu_t(accA[j][2]);
        float y3 = silu_t(accA[j][3]);
        *(uint32_t*)(wb + grp*WB_ROW + col*2)     = pack_h2(y0, y1);
        *(uint32_t*)(wb + (grp+8)*WB_ROW + col*2) = pack_h2(y2, y3);
      }
    }
    __syncwarp();

    // ---- TP phase: depth-2 prefetch ring, compute inline (R12 body) ----
    int ecount = E - base_e;
    if (ecount > 16) ecount = 16;

    Pref pf[2];
    pf_load(pf[0], base_e, lane, nf, evec, eidx);
    if (ecount > 1) pf_load(pf[1], base_e + 1, lane, nf, evec, eidx);

    #pragma unroll 2
    for (int el = 0; el < ecount; ++el){
      // consume slot el&1
      int dst = pf[el&1].dst;
      float vx = pf[el&1].vx, vy = pf[el&1].vy, vz = pf[el&1].vz;
      float x0v = pf[el&1].x0;
      float x1a = pf[el&1].x1a, x1b = pf[el&1].x1b, x1c = pf[el&1].x1c;

      // refill the slot just consumed with edge el+2 (depth-2)
      if (el + 2 < ecount)
        pf_load(pf[el&1], base_e + el + 2, lane, nf, evec, eidx);

      float nrm = sqrtf(vx*vx + vy*vy + vz*vz);
      float inv = __fdividef(1.0f, nrm + 1e-12f);
      float X = vx*inv, Yv = vy*inv, Z = vz*inv;
      const float S3 = 1.7320508075688772f;
      float Y0a[1] = {1.0f};
      float Y1a[3] = {Yv, Z, X};
      float Y2a[5] = {S3*X*Yv, S3*Yv*Z, 0.5f*(3.0f*Z*Z - 1.0f), S3*X*Z, 0.5f*S3*(X*X - Yv*Yv)};

      float x0[1] = { x0v };
      float x1[3] = { x1a, x1b, x1c };

      const __half* wr = (const __half*)(wb + el*WB_ROW);
      float o0[1] = {0.f};
      float o1[3] = {0.f,0.f,0.f};
      float o2[5] = {0.f,0.f,0.f,0.f,0.f};

      float wp0 = __half2float(wr[0*CMUL + lane]);
      float wp1 = __half2float(wr[1*CMUL + lane]);
      float wp2 = __half2float(wr[2*CMUL + lane]);
      float wp3 = __half2float(wr[3*CMUL + lane]);
      float wp4 = __half2float(wr[4*CMUL + lane]);
      float wp5 = __half2float(wr[5*CMUL + lane]);
      float wp6 = __half2float(wr[6*CMUL + lane]);
      float wp7 = __half2float(wr[7*CMUL + lane]);
      float wp8 = __half2float(wr[8*CMUL + lane]);

      do_path<0,0,0>(wp0, x0, Y0a, o0);
      do_path<0,1,1>(wp1, x0, Y1a, o1);
      do_path<0,2,2>(wp2, x0, Y2a, o2);
      do_path<1,0,1>(wp3, x1, Y0a, o1);
      do_path<1,1,0>(wp4, x1, Y1a, o0);
      do_path<1,1,1>(wp5, x1, Y1a, o1);
      do_path<1,1,2>(wp6, x1, Y1a, o2);
      do_path<1,2,1>(wp7, x1, Y2a, o1);
      do_path<1,2,2>(wp8, x1, Y2a, o2);

      // stage message (strides 1/3/5: conflict-free)
      sbw[lane] = o0[0];
      #pragma unroll
      for (int c = 0; c < 3; ++c) sbw[CMUL + 3*lane + c] = o1[c];
      #pragma unroll
      for (int c = 0; c < 5; ++c) sbw[4*CMUL + 5*lane + c] = o2[c];
      __syncwarp();

      float* orow = out + (size_t)dst * NW;
      #pragma unroll
      for (int p = 0; p < 9; ++p)
        atomicAdd(orow + p*32 + lane, sbw[p*32 + lane]);
      __syncwarp();
    }
  }
}

// ============================================================
// Launch
// ============================================================
extern "C" void kernel_launch(void* const* d_in, const int* in_sizes, int n_in,
                              void* d_out, int out_size){
  const float* nf = (const float*)d_in[0];
  const float* ef = (const float*)d_in[1];
  const float* ev = (const float*)d_in[2];
  const int*   ei = (const int*)  d_in[3];
  const float* W0 = (const float*)d_in[4];
  const float* W1 = (const float*)d_in[5];
  const float* W2 = (const float*)d_in[6];
  float* out = (float*)d_out;

  int E = in_sizes[2] / 3;
  if (E > MAX_E) E = MAX_E;

  cudaMemsetAsync(d_out, 0, (size_t)out_size * sizeof(float), 0);

  cudaFuncSetAttribute(fused_kernel, cudaFuncAttributeMaxDynamicSharedMemorySize, SM_TOT);
  fused_kernel<<<148, FT_THREADS, SM_TOT>>>(nf, ef, ev, ei, W0, W1, W2, out, E);
}

// round 15
// speedup vs baseline: 1.2088x; 1.0539x over previous
#include <cuda_runtime.h>
#include <cuda_fp16.h>
#include <cstdint>
#include <cstddef>

// ============================================================
// Problem constants
// ============================================================
#define MAX_E   320000
#define NRBF    16
#define DH      64
#define NW      288
#define CMUL    32

// ============================================================
// Compile-time Clebsch-Gordan (exact port of the reference math)
// ============================================================
struct CD { double re, im; };
__host__ __device__ constexpr CD cmulc(CD a, CD b){ return CD{a.re*b.re - a.im*b.im, a.re*b.im + a.im*b.re}; }
__host__ __device__ constexpr CD conjc(CD a){ return CD{a.re, -a.im}; }
__host__ __device__ constexpr double cfact(int n){ double r=1.0; for(int i=2;i<=n;++i) r*= (double)i; return r; }
__host__ __device__ constexpr double csqrt(double x){
  if (x <= 0.0) return 0.0;
  double r = x < 1.0 ? 1.0 : x;
  for (int i=0;i<200;++i) r = 0.5*(r + x/r);
  return r;
}
__host__ __device__ constexpr double cgc(int l1,int l2,int l3,int m1,int m2){
  int m3 = m1+m2;
  if (m3 < -l3 || m3 > l3) return 0.0;
  double pref = csqrt((double)(2*l3+1)*cfact(l1+l2-l3)*cfact(l1-l2+l3)*cfact(-l1+l2+l3)/cfact(l1+l2+l3+1));
  pref *= csqrt(cfact(l3+m3)*cfact(l3-m3)*cfact(l1-m1)*cfact(l1+m1)*cfact(l2-m2)*cfact(l2+m2));
  double s = 0.0;
  for (int k=0;k<=l1+l2-l3;++k){
    int a1=l1+l2-l3-k, a2=l1-m1-k, a3=l2+m2-k, a4=l3-l2+m1+k, a5=l3-l1-m2+k;
    if (a1<0||a2<0||a3<0||a4<0||a5<0) continue;
    double d = cfact(k)*cfact(a1)*cfact(a2)*cfact(a3)*cfact(a4)*cfact(a5);
    s += ((k&1)? -1.0 : 1.0)/d;
  }
  return pref*s;
}
struct UMat { CD u[5][5]; };
__host__ __device__ constexpr UMat makeU(int l){
  UMat U{};
  const double s = 1.0/csqrt(2.0);
  U.u[l][l] = CD{1.0, 0.0};
  for (int m=1;m<=l;++m){
    double sg = (m&1)? -1.0 : 1.0;
    U.u[l+m][l+m] = CD{sg*s, 0.0};
    U.u[l+m][l-m] = CD{s, 0.0};
    U.u[l-m][l-m] = CD{0.0, s};
    U.u[l-m][l+m] = CD{0.0, -sg*s};
  }
  return U;
}
struct CG3 { double v[5][5][5]; };
__host__ __device__ constexpr CG3 make_cg(int l1,int l2,int l3){
  UMat U1 = makeU(l1), U2 = makeU(l2), U3 = makeU(l3);
  int n1=2*l1+1, n2=2*l2+1, n3=2*l3+1;
  double tre[5][5][5] = {}, tim[5][5][5] = {};
  double mre=0.0, mim=0.0;
  for (int a=0;a<n1;++a) for (int b=0;b<n2;++b) for (int c=0;c<n3;++c){
    CD acc{0.0,0.0};
    for (int m=0;m<n1;++m) for (int n=0;n<n2;++n){
      int o = (m-l1)+(n-l2)+l3;
      if (o < 0 || o >= n3) continue;
      double cg = cgc(l1,l2,l3, m-l1, n-l2);
      if (cg == 0.0) continue;
      CD t = cmulc(cmulc(U1.u[a][m], U2.u[b][n]), conjc(U3.u[c][o]));
      acc.re += t.re*cg; acc.im += t.im*cg;
    }
    tre[a][b][c]=acc.re; tim[a][b][c]=acc.im;
    double ar = acc.re<0.0?-acc.re:acc.re;
    double ai = acc.im<0.0?-acc.im:acc.im;
    if (ar>mre) mre=ar;
    if (ai>mim) mim=ai;
  }
  CG3 R{};
  for (int a=0;a<n1;++a) for (int b=0;b<n2;++b) for (int c=0;c<n3;++c){
    double vv = (mre >= mim) ? tre[a][b][c] : tim[a][b][c];
    if (vv < 1e-12 && vv > -1e-12) vv = 0.0;
    R.v[a][b][c] = vv;
  }
  return R;
}

// tanh-based silu: silu(x) = h + h*tanh(h), h = x/2.
__device__ __forceinline__ float silu_t(float x){
  float h = 0.5f * x;
  float t;
  asm("tanh.approx.f32 %0, %1;" : "=f"(t) : "f"(h));
  return fmaf(h, t, h);
}

#define INV2048 4.8828125e-4f

// ============================================================
// mma.sync m16n8k16 fp16 + ldmatrix
// ============================================================
__device__ __forceinline__ void mma16816(float d[4], const uint32_t a[4], const uint32_t b[2]){
  asm volatile("mma.sync.aligned.m16n8k16.row.col.f32.f16.f16.f32 "
    "{%0,%1,%2,%3}, {%4,%5,%6,%7}, {%8,%9}, {%0,%1,%2,%3};"
    : "+f"(d[0]), "+f"(d[1]), "+f"(d[2]), "+f"(d[3])
    : "r"(a[0]), "r"(a[1]), "r"(a[2]), "r"(a[3]), "r"(b[0]), "r"(b[1]));
}
__device__ __forceinline__ void ldm4(uint32_t addr, uint32_t* r){
  asm volatile("ldmatrix.sync.aligned.m8n8.x4.shared.b16 {%0,%1,%2,%3}, [%4];"
    : "=r"(r[0]), "=r"(r[1]), "=r"(r[2]), "=r"(r[3]) : "r"(addr));
}

// split into fp16 hi + fp16 residual scaled by 2048
__device__ __forceinline__ void split2h(float y0, float y1, uint32_t& hi, uint32_t& lo){
  uint32_t h;
  asm("cvt.rn.f16x2.f32 %0, %1, %2;" : "=r"(h) : "f"(y1), "f"(y0));
  __half2 hh = *reinterpret_cast<__half2*>(&h);
  float2 hf = __half22float2(hh);
  float r0 = (y0 - hf.x) * 2048.0f;
  float r1 = (y1 - hf.y) * 2048.0f;
  uint32_t l;
  asm("cvt.rn.f16x2.f32 %0, %1, %2;" : "=r"(l) : "f"(r1), "f"(r0));
  hi = h; lo = l;
}
__device__ __forceinline__ uint32_t pack_h2(float y0, float y1){
  uint32_t h;
  asm("cvt.rn.f16x2.f32 %0, %1, %2;" : "=r"(h) : "f"(y1), "f"(y0));
  return h;
}

// ============================================================
// Packed f32x2 ops (base-ISA PTX; proven on this harness in R2-R5)
// ============================================================
union F2U { float2 f; unsigned long long u; };
__device__ __forceinline__ float2 ffma2(float2 a, float2 b, float2 c){
  F2U A,B,C,D; A.f=a; B.f=b; C.f=c;
  asm("fma.rn.f32x2 %0, %1, %2, %3;" : "=l"(D.u) : "l"(A.u), "l"(B.u), "l"(C.u));
  return D.f;
}
__device__ __forceinline__ float2 fmul2(float2 a, float2 b){
  F2U A,B,D; A.f=a; B.f=b;
  asm("mul.rn.f32x2 %0, %1, %2;" : "=l"(D.u) : "l"(A.u), "l"(B.u));
  return D.f;
}
__device__ __forceinline__ float2 fadd2(float2 a, float2 b){
  F2U A,B,D; A.f=a; B.f=b;
  asm("add.rn.f32x2 %0, %1, %2;" : "=l"(D.u) : "l"(A.u), "l"(B.u));
  return D.f;
}

// ============================================================
// SMEM layout (bytes).
// ============================================================
#define SM_W0   0          // 64 * 48   = 3072
#define SM_W1   3072       // 64 * 144  = 9216
#define SM_W2   12288      // 288 * 144 = 41472
#define WB_ROW  592
#define WB_WARP (16*WB_ROW)            // 9472
#define SM_WBUF 53760
#define SM_SB   (SM_WBUF + 16*WB_WARP) // 205312
#define SM_TOT  (SM_SB + 16*NW*4)      // 223744

#define FT_THREADS 512   // 16 warps, each autonomous on 16-edge tiles

// Packed (edge-pair) CG tensor-product path.
template<int L1, int L2, int L3>
__device__ __forceinline__ void do_path2(float2 wp, const float2* x, const float2* Y, float2* o){
  constexpr CG3 cg = make_cg(L1, L2, L3);
  #pragma unroll
  for (int a = 0; a < 2*L1+1; ++a){
    float2 wx = fmul2(wp, x[a]);
    #pragma unroll
    for (int b = 0; b < 2*L2+1; ++b){
      #pragma unroll
      for (int c = 0; c < 2*L3+1; ++c){
        const float v = (float)cg.v[a][b][c];
        if (v != 0.0f){
          if (L2 == 0){
            // Y[0] == 1 and v == 1 for these paths
            o[c] = fadd2(o[c], wx);
          } else if (v == 1.0f){
            o[c] = ffma2(wx, Y[b], o[c]);
          } else {
            float2 vv = make_float2(v, v);
            o[c] = ffma2(wx, fmul2(vv, Y[b]), o[c]);
          }
        }
      }
    }
  }
}

__global__ __launch_bounds__(FT_THREADS)
void fused_kernel(const float* __restrict__ nf,
                  const float* __restrict__ ef,
                  const float* __restrict__ evec,
                  const int*   __restrict__ eidx,
                  const float* __restrict__ W0,
                  const float* __restrict__ W1,
                  const float* __restrict__ W2,
                  float* __restrict__ out,
                  int E){
  extern __shared__ char sm[];
  uint32_t sm32 = (uint32_t)__cvta_generic_to_shared(sm);
  int t = threadIdx.x;
  int lane = t & 31, wid = t >> 5;
  int grp = lane >> 2, qt = lane & 3;

  const uint32_t offB48  = (uint32_t)(lane>>4)*384  + (uint32_t)(lane&7)*48  + (uint32_t)((lane>>3)&1)*16;
  const uint32_t offB144 = (uint32_t)(lane>>4)*1152 + (uint32_t)(lane&7)*144 + (uint32_t)((lane>>3)&1)*16;

  // ---- stage fp16 weights once ----
  for (int idx = t; idx < 16*64; idx += FT_THREADS){
    int k = idx >> 6, n = idx & 63;
    *(__half*)(sm + SM_W0 + n*48 + k*2) = __float2half_rn(W0[idx]);
  }
  for (int idx = t; idx < 64*64; idx += FT_THREADS){
    int k = idx >> 6, n = idx & 63;
    *(__half*)(sm + SM_W1 + n*144 + k*2) = __float2half_rn(W1[idx]);
  }
  for (int idx = t; idx < 64*288; idx += FT_THREADS){
    int k = idx / 288, n = idx % 288;
    *(__half*)(sm + SM_W2 + n*144 + k*2) = __float2half_rn(W2[idx]);
  }
  __syncthreads();   // only block barrier in the kernel

  char* wb = sm + SM_WBUF + wid * WB_WARP;
  float* sbw = (float*)(sm + SM_SB + wid * NW * 4);

  int ntiles = (E + 15) >> 4;
  int gwarp  = blockIdx.x * (FT_THREADS/32) + wid;
  int stride = gridDim.x * (FT_THREADS/32);

  for (int tl = gwarp; tl < ntiles; tl += stride){
    int base_e = tl * 16;
    int e0 = base_e + grp;
    int e1 = e0 + 8;
    int ec0 = (e0 < E) ? e0 : E-1;
    int ec1 = (e1 < E) ? e1 : E-1;

    // ---- A1 fragments straight from ef (hi + scaled residual) ----
    uint32_t a1h[4], a1l[4];
    {
      float2 p00 = *(const float2*)(ef + (size_t)ec0*NRBF + 2*qt);
      float2 p10 = *(const float2*)(ef + (size_t)ec1*NRBF + 2*qt);
      float2 p01 = *(const float2*)(ef + (size_t)ec0*NRBF + 8 + 2*qt);
      float2 p11 = *(const float2*)(ef + (size_t)ec1*NRBF + 8 + 2*qt);
      split2h(p00.x, p00.y, a1h[0], a1l[0]);
      split2h(p10.x, p10.y, a1h[1], a1l[1]);
      split2h(p01.x, p01.y, a1h[2], a1l[2]);
      split2h(p11.x, p11.y, a1h[3], a1l[3]);
    }

    // ---- Layer 1: 16 -> 64, A split-2 ----
    uint32_t a2h[4][4], a2l[4][4];
    #pragma unroll
    for (int g = 0; g < 2; ++g){
      float accA[4][4], accB[4][4];
      #pragma unroll
      for (int j=0;j<4;++j)
        #pragma unroll
        for (int q=0;q<4;++q){ accA[j][q]=0.f; accB[j][q]=0.f; }
      uint32_t b01[4], b23[4];
      ldm4(sm32 + SM_W0 + (uint32_t)((g*4+0)*8)*48 + offB48, b01);
      ldm4(sm32 + SM_W0 + (uint32_t)((g*4+2)*8)*48 + offB48, b23);
      mma16816(accA[0], a1h, b01+0); mma16816(accA[1], a1h, b01+2);
      mma16816(accA[2], a1h, b23+0); mma16816(accA[3], a1h, b23+2);
      mma16816(accB[0], a1l, b01+0); mma16816(accB[1], a1l, b01+2);
      mma16816(accB[2], a1l, b23+0); mma16816(accB[3], a1l, b23+2);
      #pragma unroll
      for (int j=0;j<4;++j){
        int nt = g*4 + j, ks = nt >> 1, ix = (nt & 1) * 2;
        float y0 = silu_t(fmaf(accB[j][0], INV2048, accA[j][0]));
        float y1 = silu_t(fmaf(accB[j][1], INV2048, accA[j][1]));
        float y2 = silu_t(fmaf(accB[j][2], INV2048, accA[j][2]));
        float y3 = silu_t(fmaf(accB[j][3], INV2048, accA[j][3]));
        split2h(y0, y1, a2h[ks][ix],   a2l[ks][ix]);
        split2h(y2, y3, a2h[ks][ix+1], a2l[ks][ix+1]);
      }
    }

    // ---- Layer 2: 64 -> 64, A split-2; output hi-only fragments ----
    uint32_t a3h[4][4];
    #pragma unroll
    for (int g = 0; g < 2; ++g){
      float accA[4][4], accB[4][4];
      #pragma unroll
      for (int j=0;j<4;++j)
        #pragma unroll
        for (int q=0;q<4;++q){ accA[j][q]=0.f; accB[j][q]=0.f; }
      #pragma unroll
      for (int ks = 0; ks < 4; ++ks){
        uint32_t b01[4], b23[4];
        ldm4(sm32 + SM_W1 + (uint32_t)((g*4+0)*8)*144 + (uint32_t)ks*32 + offB144, b01);
        ldm4(sm32 + SM_W1 + (uint32_t)((g*4+2)*8)*144 + (uint32_t)ks*32 + offB144, b23);
        mma16816(accA[0], a2h[ks], b01+0); mma16816(accA[1], a2h[ks], b01+2);
        mma16816(accA[2], a2h[ks], b23+0); mma16816(accA[3], a2h[ks], b23+2);
        mma16816(accB[0], a2l[ks], b01+0); mma16816(accB[1], a2l[ks], b01+2);
        mma16816(accB[2], a2l[ks], b23+0); mma16816(accB[3], a2l[ks], b23+2);
      }
      #pragma unroll
      for (int j=0;j<4;++j){
        int nt = g*4 + j, ks = nt >> 1, ix = (nt & 1) * 2;
        float y0 = silu_t(fmaf(accB[j][0], INV2048, accA[j][0]));
        float y1 = silu_t(fmaf(accB[j][1], INV2048, accA[j][1]));
        float y2 = silu_t(fmaf(accB[j][2], INV2048, accA[j][2]));
        float y3 = silu_t(fmaf(accB[j][3], INV2048, accA[j][3]));
        a3h[ks][ix]   = pack_h2(y0, y1);
        a3h[ks][ix+1] = pack_h2(y2, y3);
      }
    }

    // ---- Layer 3: 64 -> 288, A hi-only; write into per-warp wbuf ----
    #pragma unroll 1
    for (int g = 0; g < 9; ++g){
      float accA[4][4];
      #pragma unroll
      for (int j=0;j<4;++j)
        #pragma unroll
        for (int q=0;q<4;++q) accA[j][q]=0.f;
      #pragma unroll
      for (int ks = 0; ks < 4; ++ks){
        uint32_t b01[4], b23[4];
        ldm4(sm32 + SM_W2 + (uint32_t)((g*4+0)*8)*144 + (uint32_t)ks*32 + offB144, b01);
        ldm4(sm32 + SM_W2 + (uint32_t)((g*4+2)*8)*144 + (uint32_t)ks*32 + offB144, b23);
        mma16816(accA[0], a3h[ks], b01+0); mma16816(accA[1], a3h[ks], b01+2);
        mma16816(accA[2], a3h[ks], b23+0); mma16816(accA[3], a3h[ks], b23+2);
      }
      #pragma unroll
      for (int j=0;j<4;++j){
        int col = (g*4+j)*8 + 2*qt;
        float y0 = silu_t(accA[j][0]);
        float y1 = silu_t(accA[j][1]);
        float y2 = silu_t(accA[j][2]);
        float y3 = silu_t(accA[j][3]);
        *(uint32_t*)(wb + grp*WB_ROW + col*2)     = pack_h2(y0, y1);
        *(uint32_t*)(wb + (grp+8)*WB_ROW + col*2) = pack_h2(y2, y3);
      }
    }
    __syncwarp();

    // ---- TP phase: edge PAIRS packed into f32x2 ----
    int ecount = E - base_e;
    if (ecount > 16) ecount = 16;
    int npairs = (ecount + 1) >> 1;

    #pragma unroll 1
    for (int pi = 0; pi < npairs; ++pi){
      int eA = base_e + 2*pi;
      bool vB = (2*pi + 1) < ecount;
      int eB = vB ? (eA + 1) : eA;

      // meta + gathers for both edges
      int srcA = eidx[2*eA+0], dstA = eidx[2*eA+1];
      int srcB = eidx[2*eB+0], dstB = eidx[2*eB+1];
      float vxA = evec[3*(size_t)eA+0], vyA = evec[3*(size_t)eA+1], vzA = evec[3*(size_t)eA+2];
      float vxB = evec[3*(size_t)eB+0], vyB = evec[3*(size_t)eB+1], vzB = evec[3*(size_t)eB+2];
      const float* nrA = nf + (size_t)srcA * (4*CMUL);
      const float* nrB = nf + (size_t)srcB * (4*CMUL);
      float2 x0p  = make_float2(nrA[lane], nrB[lane]);
      float2 x1p[3];
      x1p[0] = make_float2(nrA[CMUL + 3*lane + 0], nrB[CMUL + 3*lane + 0]);
      x1p[1] = make_float2(nrA[CMUL + 3*lane + 1], nrB[CMUL + 3*lane + 1]);
      x1p[2] = make_float2(nrA[CMUL + 3*lane + 2], nrB[CMUL + 3*lane + 2]);

      // spherical harmonics per edge, then packed
      float2 Y1p[3], Y2p[5];
      {
        float nrmA = sqrtf(vxA*vxA + vyA*vyA + vzA*vzA);
        float nrmB = sqrtf(vxB*vxB + vyB*vyB + vzB*vzB);
        float iA = __fdividef(1.0f, nrmA + 1e-12f);
        float iB = __fdividef(1.0f, nrmB + 1e-12f);
        float XA = vxA*iA, YA = vyA*iA, ZA = vzA*iA;
        float XB = vxB*iB, YB = vyB*iB, ZB = vzB*iB;
        const float S3 = 1.7320508075688772f;
        Y1p[0] = make_float2(YA, YB);
        Y1p[1] = make_float2(ZA, ZB);
        Y1p[2] = make_float2(XA, XB);
        Y2p[0] = make_float2(S3*XA*YA, S3*XB*YB);
        Y2p[1] = make_float2(S3*YA*ZA, S3*YB*ZB);
        Y2p[2] = make_float2(0.5f*(3.0f*ZA*ZA - 1.0f), 0.5f*(3.0f*ZB*ZB - 1.0f));
        Y2p[3] = make_float2(S3*XA*ZA, S3*XB*ZB);
        Y2p[4] = make_float2(0.5f*S3*(XA*XA - YA*YA), 0.5f*S3*(XB*XB - YB*YB));
      }

      // weights for both edges, packed
      const __half* wrA = (const __half*)(wb + (2*pi+0)*WB_ROW);
      const __half* wrB = (const __half*)(wb + (2*pi+1)*WB_ROW);
      float2 wpp[9];
      #pragma unroll
      for (int p = 0; p < 9; ++p)
        wpp[p] = make_float2(__half2float(wrA[p*CMUL + lane]),
                             __half2float(wrB[p*CMUL + lane]));

      // packed CG contraction
      float2 o[9];
      #pragma unroll
      for (int q = 0; q < 9; ++q) o[q] = make_float2(0.f, 0.f);
      float2* o0 = o;      // 1
      float2* o1 = o + 1;  // 3
      float2* o2 = o + 4;  // 5

      do_path2<0,0,0>(wpp[0], &x0p, Y1p, o0);
      do_path2<0,1,1>(wpp[1], &x0p, Y1p, o1);
      do_path2<0,2,2>(wpp[2], &x0p, Y2p, o2);
      do_path2<1,0,1>(wpp[3], x1p,  Y1p, o1);
      do_path2<1,1,0>(wpp[4], x1p,  Y1p, o0);
      do_path2<1,1,1>(wpp[5], x1p,  Y1p, o1);
      do_path2<1,1,2>(wpp[6], x1p,  Y1p, o2);
      do_path2<1,2,1>(wpp[7], x1p,  Y2p, o1);
      do_path2<1,2,2>(wpp[8], x1p,  Y2p, o2);

      // ---- tail A ----
      sbw[lane] = o[0].x;
      #pragma unroll
      for (int c = 0; c < 3; ++c) sbw[CMUL + 3*lane + c] = o[1+c].x;
      #pragma unroll
      for (int c = 0; c < 5; ++c) sbw[4*CMUL + 5*lane + c] = o[4+c].x;
      __syncwarp();
      {
        float* orow = out + (size_t)dstA * NW;
        #pragma unroll
        for (int p = 0; p < 9; ++p)
          atomicAdd(orow + p*32 + lane, sbw[p*32 + lane]);
      }
      __syncwarp();

      // ---- tail B ----
      if (vB){
        sbw[lane] = o[0].y;
        #pragma unroll
        for (int c = 0; c < 3; ++c) sbw[CMUL + 3*lane + c] = o[1+c].y;
        #pragma unroll
        for (int c = 0; c < 5; ++c) sbw[4*CMUL + 5*lane + c] = o[4+c].y;
        __syncwarp();
        float* orow = out + (size_t)dstB * NW;
        #pragma unroll
        for (int p = 0; p < 9; ++p)
          atomicAdd(orow + p*32 + lane, sbw[p*32 + lane]);
        __syncwarp();
      }
    }
  }
}

// ============================================================
// Launch
// ============================================================
extern "C" void kernel_launch(void* const* d_in, const int* in_sizes, int n_in,
                              void* d_out, int out_size){
  const float* nf = (const float*)d_in[0];
  const float* ef = (const float*)d_in[1];
  const float* ev = (const float*)d_in[2];
  const int*   ei = (const int*)  d_in[3];
  const float* W0 = (const float*)d_in[4];
  const float* W1 = (const float*)d_in[5];
  const float* W2 = (const float*)d_in[6];
  float* out = (float*)d_out;

  int E = in_sizes[2] / 3;
  if (E > MAX_E) E = MAX_E;

  cudaMemsetAsync(d_out, 0, (size_t)out_size * sizeof(float), 0);

  cudaFuncSetAttribute(fused_kernel, cudaFuncAttributeMaxDynamicSharedMemorySize, SM_TOT);
  fused_kernel<<<148, FT_THREADS, SM_TOT>>>(nf, ef, ev, ei, W0, W1, W2, out, E);
}